// round 16
// baseline (speedup 1.0000x reference)
#include <cuda_runtime.h>
#include <cuda_fp16.h>
#include <cstdint>
#include <math.h>

#define B_   4
#define S_   2048
#define E_   1024
#define NH_  16
#define HD_  64
#define M_   (B_ * S_)        // 8192
#define QKV_ (3 * NH_ * HD_)  // 3072
#define NHD_ (NH_ * HD_)      // 1024
#define KD   1024
#define NCH  (KD / 32)        // 32 chunks of 32 k (16 kpairs)
#define AP2  20               // A smem pitch (u32 units)
#define BP2  136              // B smem pitch (u32 units)
#define KP2  72               // flash K/V smem pitch (u32)
#define PP2  36               // flash Q-stage pitch (u32)
#define FSS  (32 * KP2)       // flash stage size per operand (u32)
#define SCALE_LOG2E 0.1803368801111204f   // (1/sqrt(64)) * log2(e)

// ---- scratch ----------------------------------------------------------------
// RULE (R3-R10): __device__ globals may ONLY be referenced from device code.
__device__ __half   g_q[B_ * NH_ * S_ * HD_];        // [B,N,S,H]
__device__ uint32_t g_k[B_ * NH_ * (HD_ / 2) * S_];  // [B,N,H/2,S] packed half2(d,d+1)
__device__ __half   g_v[B_ * NH_ * S_ * HD_];        // [B,N,S,H]
__device__ uint32_t g_vp[B_ * NH_ * (S_ / 2) * HD_]; // [B,N,S/2,H] packed half2(s,s+1)
__device__ __half   g_ao[B_ * S_ * NHD_];            // [B,S,N*H]
__device__ __half   g_xh[M_ * E_];                   // x in fp16
__device__ uint32_t g_wqp[(KD / 2) * QKV_];          // W_qkv packed half2-kpair
__device__ uint32_t g_wop[(KD / 2) * NHD_];          // W_out packed

// ---------------- helpers ---------------------------------------------------
__device__ __forceinline__ uint32_t pack2(float lo, float hi) {
    uint32_t r;
    asm("cvt.rn.f16x2.f32 %0, %1, %2;" : "=r"(r) : "f"(hi), "f"(lo));
    return r;
}
__device__ __forceinline__ float ex2f(float x) {
    float r;
    asm("ex2.approx.f32 %0, %1;" : "=f"(r) : "f"(x));
    return r;
}
__device__ __forceinline__ uint32_t ex2h2(uint32_t x) {
    uint32_t r;
    asm("ex2.approx.f16x2 %0, %1;" : "=r"(r) : "r"(x));
    return r;
}
#define MMA_F16(c0, c1, c2, c3, a0, a1, a2, a3, b0, b1)                       \
    asm volatile(                                                             \
        "mma.sync.aligned.m16n8k16.row.col.f32.f16.f16.f32 "                  \
        "{%0,%1,%2,%3}, {%4,%5,%6,%7}, {%8,%9}, {%0,%1,%2,%3};"               \
        : "+f"(c0), "+f"(c1), "+f"(c2), "+f"(c3)                              \
        : "r"(a0), "r"(a1), "r"(a2), "r"(a3), "r"(b0), "r"(b1))

// ---------------------------------------------------------------------------
// prep: x (fp32) -> g_xh (fp16)
__global__ __launch_bounds__(256)
void cvt_x_kernel(const float* __restrict__ x)
{
    const size_t i = ((size_t)blockIdx.x * 256 + threadIdx.x) * 8;
    const float4 v0 = *(const float4*)(x + i);
    const float4 v1 = *(const float4*)(x + i + 4);
    uint4 o;
    o.x = pack2(v0.x, v0.y); o.y = pack2(v0.z, v0.w);
    o.z = pack2(v1.x, v1.y); o.w = pack2(v1.z, v1.w);
    *(uint4*)(g_xh + i) = o;
}
// prep: W [K][NW] fp32 -> g_wqp/g_wop packed half2-kpair
template <int MODE>
__global__ __launch_bounds__(256)
void pack_w_kernel(const float* __restrict__ W)
{
    const int NW = (MODE == 1) ? QKV_ : NHD_;
    uint32_t* Wp = (MODE == 1) ? g_wqp : g_wop;
    const int i  = blockIdx.x * 256 + threadIdx.x;
    const int kp = i / (NW / 4);
    const int c4 = (i % (NW / 4)) * 4;
    const float* w0 = W + (size_t)(2 * kp) * NW + c4;
    const float4 a = *(const float4*)w0;
    const float4 b = *(const float4*)(w0 + NW);
    uint4 o;
    o.x = pack2(a.x, b.x); o.y = pack2(a.y, b.y);
    o.z = pack2(a.z, b.z); o.w = pack2(a.w, b.w);
    *(uint4*)(Wp + (size_t)kp * NW + c4) = o;
}
// prep: g_v -> g_vp [B,N,S/2,H]: vp[sp][h] = half2(V[2sp][h], V[2sp+1][h])
__global__ __launch_bounds__(256)
void pack_v_kernel()
{
    const int i   = blockIdx.x * 256 + threadIdx.x;
    const int h2  = i & 31;
    const int spg = i >> 5;
    const int bn  = spg >> 10;
    const int spl = spg & 1023;
    const uint32_t* v32 = (const uint32_t*)g_v;
    const uint32_t a = v32[((size_t)bn * S_ + 2 * spl) * 32 + h2];
    const uint32_t b = v32[((size_t)bn * S_ + 2 * spl + 1) * 32 + h2];
    uint2 o;
    o.x = __byte_perm(a, b, 0x5410);
    o.y = __byte_perm(a, b, 0x7632);
    *(uint2*)(g_vp + (size_t)spg * 64 + 2 * h2) = o;
}

// ---------------------------------------------------------------------------
// FP16 mma.sync GEMM (unchanged from R13-R15): 4 warps, warp tile 64x64.
template <int MODE>
__global__ __launch_bounds__(128)
void mma_gemm(const float* __restrict__ bias, float* __restrict__ Cout)
{
    const int NW = (MODE == 1) ? QKV_ : NHD_;
    const uint32_t* __restrict__ Wp = (MODE == 1) ? g_wqp : g_wop;
    extern __shared__ uint32_t smu[];
    uint32_t* As = smu;
    uint32_t* Bs = smu + 2 * 128 * AP2;

    const int tid  = threadIdx.x;
    const int wid  = tid >> 5;
    const int lane = tid & 31;
    const int warpM = wid & 1;
    const int warpN = wid >> 1;
    const int t4  = lane >> 2;
    const int tm4 = lane & 3;

    const int bn = blockIdx.x * 128, bm = blockIdx.y * 128;
    const __half* Ag = (MODE == 1) ? g_xh : g_ao;

    const int ar   = (tid >> 2);
    const int aseg = (tid & 3) * 4;
    const int brow = (tid >> 5);
    const int bc4  = (tid & 31) * 4;
    const __half*   Ap = Ag + (size_t)(bm + ar) * KD + aseg * 2;
    const uint32_t* Bp = Wp + (size_t)brow * NW + bn + bc4;

    uint4 pa[4], pb[4];
#pragma unroll
    for (int q = 0; q < 4; q++) {
        pa[q] = *(const uint4*)(Ap + (size_t)(q * 32) * KD);
        pb[q] = *(const uint4*)(Bp + (size_t)(q * 4) * NW);
    }

    float acc[4][8][4];
#pragma unroll
    for (int mf = 0; mf < 4; mf++)
#pragma unroll
        for (int nf = 0; nf < 8; nf++)
#pragma unroll
            for (int e = 0; e < 4; e++) acc[mf][nf][e] = 0.f;

#pragma unroll
    for (int q = 0; q < 4; q++) {
        *(uint4*)(As + (ar + q * 32) * AP2 + aseg) = pa[q];
        *(uint4*)(Bs + (brow + q * 4) * BP2 + bc4) = pb[q];
    }
    __syncthreads();

    for (int ch = 0; ch < NCH; ch++) {
        if (ch + 1 < NCH) {
            const int kh = (ch + 1) * 32;
            const int kr = (ch + 1) * 16;
#pragma unroll
            for (int q = 0; q < 4; q++) {
                pa[q] = *(const uint4*)(Ap + (size_t)(q * 32) * KD + kh);
                pb[q] = *(const uint4*)(Bp + (size_t)(kr + q * 4) * NW);
            }
        }

        const uint32_t* Sa = As + (ch & 1) * 128 * AP2;
        const uint32_t* Sb = Bs + (ch & 1) * 16 * BP2;
#pragma unroll
        for (int s = 0; s < 2; s++) {
            const int kk = s * 8;
            uint32_t a[4][4], b[8][2];
#pragma unroll
            for (int mf = 0; mf < 4; mf++) {
                const uint32_t* pav = Sa + (warpM * 64 + mf * 16 + t4) * AP2 + kk + tm4;
                a[mf][0] = pav[0];
                a[mf][1] = pav[8 * AP2];
                a[mf][2] = pav[4];
                a[mf][3] = pav[8 * AP2 + 4];
            }
#pragma unroll
            for (int nf = 0; nf < 8; nf++) {
                const uint32_t* pbv = Sb + (kk + tm4) * BP2 + warpN * 64 + nf * 8 + t4;
                b[nf][0] = pbv[0];
                b[nf][1] = pbv[4 * BP2];
            }
#pragma unroll
            for (int mf = 0; mf < 4; mf++)
#pragma unroll
                for (int nf = 0; nf < 8; nf++)
                    MMA_F16(acc[mf][nf][0], acc[mf][nf][1], acc[mf][nf][2], acc[mf][nf][3],
                            a[mf][0], a[mf][1], a[mf][2], a[mf][3],
                            b[nf][0], b[nf][1]);
        }

        if (ch + 1 < NCH) {
            uint32_t* Da = As + ((ch + 1) & 1) * 128 * AP2;
            uint32_t* Db = Bs + ((ch + 1) & 1) * 16 * BP2;
#pragma unroll
            for (int q = 0; q < 4; q++) {
                *(uint4*)(Da + (ar + q * 32) * AP2 + aseg) = pa[q];
                *(uint4*)(Db + (brow + q * 4) * BP2 + bc4) = pb[q];
            }
        }
        __syncthreads();
    }

#pragma unroll
    for (int mf = 0; mf < 4; mf++) {
#pragma unroll
        for (int nf = 0; nf < 8; nf++) {
            const int col = bn + warpN * 64 + nf * 8 + 2 * tm4;
            const float2 bv = *(const float2*)(bias + col);
#pragma unroll
            for (int half_ = 0; half_ < 2; half_++) {
                const int m = bm + warpM * 64 + mf * 16 + t4 + half_ * 8;
                const float ox = acc[mf][nf][half_ * 2 + 0] + bv.x;
                const float oy = acc[mf][nf][half_ * 2 + 1] + bv.y;
                if (MODE == 0) {
                    *(float2*)(Cout + (size_t)m * NHD_ + col) = make_float2(ox, oy);
                } else {
                    const int b = m >> 11;
                    const int s = m & (S_ - 1);
                    const int which = col >> 10;
                    const int rem   = col & 1023;
                    const int n = rem >> 6;
                    const int h = rem & 63;
                    if (which == 1) {
                        g_k[((size_t)(b * NH_ + n) * (HD_ / 2) + (h >> 1)) * S_ + s] =
                            pack2(ox, oy);
                    } else {
                        __half* dst = (which == 0) ? g_q : g_v;
                        *(uint32_t*)(dst + (((size_t)b * NH_ + n) * S_ + s) * HD_ + h) =
                            pack2(ox, oy);
                    }
                }
            }
        }
    }
}

// ---------------------------------------------------------------------------
// FP16 mma.sync causal flash attention.
// R16: 128-query CTA (8 warps), 64-key tiles. K/V global+smem traffic per MMA
// halves; loader shrinks to 2 uint4/thread/operand. Softmax per-warp code
// identical to R15 (ex2.f16x2, tensor-core row-sum via ones column).
__global__ __launch_bounds__(256)
void flash_mma()
{
    extern __shared__ uint32_t smu[];

    const int tid  = threadIdx.x;
    const int wid  = tid >> 5;          // 0..7: query rows [16w,16w+16)
    const int lane = tid & 31;
    const int t4   = lane >> 2;
    const int tm4  = lane & 3;
    const int qt   = gridDim.x - 1 - blockIdx.x;   // big causal tiles first
    const int bn   = blockIdx.y;
    const int b    = bn >> 4;
    const int n    = bn & 15;

    const __half*   Qg  = g_q + ((size_t)bn * S_ + (size_t)qt * 128) * HD_;
    const uint32_t* KgT = g_k + (size_t)bn * 32 * S_;
    const uint32_t* VgP = g_vp + (size_t)bn * (S_ / 2) * 64;

    // stage Q tile (128 rows x 32 u32; transiently in K0+V0 stage area)
    {
        const int row = tid >> 1;
        const int c0  = (tid & 1) * 16;
        const uint32_t* src = (const uint32_t*)(Qg + (size_t)row * HD_) + c0;
        uint32_t* dst = smu + row * PP2 + c0;
#pragma unroll
        for (int i = 0; i < 4; i++) ((uint4*)dst)[i] = ((const uint4*)src)[i];
    }
    __syncthreads();
    uint32_t qf[4][4];
#pragma unroll
    for (int s = 0; s < 4; s++) {
        const uint32_t* p = smu + (wid * 16 + t4) * PP2 + s * 8 + tm4;
        qf[s][0] = p[0];
        qf[s][1] = p[8 * PP2];
        qf[s][2] = p[4];
        qf[s][3] = p[8 * PP2 + 4];
    }
    __syncthreads();   // Q fully consumed before stage area is rewritten

    // loader geometry: 32 rows x 64 u32 per operand; 2 uint4 per thread
    const int lr  = tid >> 3;           // row 0..31
    const int lc8 = (tid & 7) * 8;      // u32 col base; +4 for second uint4

    // ones-column init: Vs col 64 = half2(1,1), cols 65..71 = 0 (both stages)
#pragma unroll
    for (int i = 0; i < 2; i++) {
        const int idx   = tid + i * 256;
        const int row   = idx & 31;
        const int cc    = (idx >> 5) & 7;
        const int stage = idx >> 8;
        smu[stage * 2 * FSS + FSS + row * KP2 + 64 + cc] =
            (cc == 0) ? 0x3C003C00u : 0u;
    }

    // prologue: key tile 0 -> stage 0
    {
        *(uint4*)(smu + lr * KP2 + lc8) =
            *(const uint4*)(KgT + (size_t)lr * S_ + lc8);
        *(uint4*)(smu + lr * KP2 + lc8 + 4) =
            *(const uint4*)(KgT + (size_t)lr * S_ + lc8 + 4);
        *(uint4*)(smu + FSS + lr * KP2 + lc8) =
            *(const uint4*)(VgP + (size_t)lr * 64 + lc8);
        *(uint4*)(smu + FSS + lr * KP2 + lc8 + 4) =
            *(const uint4*)(VgP + (size_t)lr * 64 + lc8 + 4);
    }
    __syncthreads();

    // of[0..7] = O columns; of[8] = l (ones-column accumulator)
    float of[9][4];
#pragma unroll
    for (int nf = 0; nf < 9; nf++)
#pragma unroll
        for (int e = 0; e < 4; e++) of[nf][e] = 0.f;
    float m0 = -1e30f, m1 = -1e30f;

    const int nK = 2 * qt + 2;          // key tiles covering [0, 128(qt+1))
    for (int kt = 0; kt < nK; kt++) {
        // prefetch next K/V tile into registers (overlaps MMAs)
        uint4 kr0, kr1, vr0, vr1;
        const bool pf = (kt + 1 < nK);
        if (pf) {
            kr0 = *(const uint4*)(KgT + (size_t)lr * S_ + (kt + 1) * 64 + lc8);
            kr1 = *(const uint4*)(KgT + (size_t)lr * S_ + (kt + 1) * 64 + lc8 + 4);
            vr0 = *(const uint4*)(VgP + (size_t)((kt + 1) * 32 + lr) * 64 + lc8);
            vr1 = *(const uint4*)(VgP + (size_t)((kt + 1) * 32 + lr) * 64 + lc8 + 4);
        }

        const uint32_t* Ks = smu + (kt & 1) * 2 * FSS;
        const uint32_t* Vs = Ks + FSS;

        // S = Q K^T
        float sf[8][4];
#pragma unroll
        for (int nf = 0; nf < 8; nf++)
#pragma unroll
            for (int e = 0; e < 4; e++) sf[nf][e] = 0.f;
#pragma unroll
        for (int s = 0; s < 4; s++) {
#pragma unroll
            for (int nf = 0; nf < 8; nf++) {
                const uint32_t* pb = Ks + (s * 8 + tm4) * KP2 + nf * 8 + t4;
                MMA_F16(sf[nf][0], sf[nf][1], sf[nf][2], sf[nf][3],
                        qf[s][0], qf[s][1], qf[s][2], qf[s][3],
                        pb[0], pb[4 * KP2]);
            }
        }

        // scale into exp2 domain + causal mask (global indices) + row max
        const bool diag = (kt >= 2 * qt);
        float mn0 = m0, mn1 = m1;
#pragma unroll
        for (int nf = 0; nf < 8; nf++) {
#pragma unroll
            for (int e = 0; e < 4; e++) {
                float v = sf[nf][e] * SCALE_LOG2E;
                if (diag) {
                    const int kcol = kt * 64 + nf * 8 + 2 * tm4 + (e & 1);
                    const int qrow = qt * 128 + wid * 16 + t4 + ((e >= 2) ? 8 : 0);
                    if (kcol > qrow) v = -1e30f;
                }
                sf[nf][e] = v;
            }
            mn0 = fmaxf(mn0, fmaxf(sf[nf][0], sf[nf][1]));
            mn1 = fmaxf(mn1, fmaxf(sf[nf][2], sf[nf][3]));
        }
        mn0 = fmaxf(mn0, __shfl_xor_sync(0xffffffffu, mn0, 1));
        mn0 = fmaxf(mn0, __shfl_xor_sync(0xffffffffu, mn0, 2));
        mn1 = fmaxf(mn1, __shfl_xor_sync(0xffffffffu, mn1, 1));
        mn1 = fmaxf(mn1, __shfl_xor_sync(0xffffffffu, mn1, 2));
        const float corr0 = ex2f(m0 - mn0);
        const float corr1 = ex2f(m1 - mn1);
        m0 = mn0; m1 = mn1;

        // exp2 in fp16x2: output = packed P A-fragment directly
        uint32_t pfr[8][2];
#pragma unroll
        for (int nf = 0; nf < 8; nf++) {
            pfr[nf][0] = ex2h2(pack2(sf[nf][0] - mn0, sf[nf][1] - mn0));
            pfr[nf][1] = ex2h2(pack2(sf[nf][2] - mn1, sf[nf][3] - mn1));
        }
        // rescale O and l accumulators
#pragma unroll
        for (int nf = 0; nf < 9; nf++) {
            of[nf][0] *= corr0; of[nf][1] *= corr0;
            of[nf][2] *= corr1; of[nf][3] *= corr1;
        }

        // O += P V  and  l += P . ones   (nf = 8 reads the ones column)
#pragma unroll
        for (int s = 0; s < 4; s++) {
            const uint32_t a0 = pfr[2 * s][0];
            const uint32_t a1 = pfr[2 * s][1];
            const uint32_t a2 = pfr[2 * s + 1][0];
            const uint32_t a3 = pfr[2 * s + 1][1];
#pragma unroll
            for (int nf = 0; nf < 9; nf++) {
                const uint32_t* pv = Vs + (s * 8 + tm4) * KP2 + nf * 8 + t4;
                MMA_F16(of[nf][0], of[nf][1], of[nf][2], of[nf][3],
                        a0, a1, a2, a3, pv[0], pv[4 * KP2]);
            }
        }

        // store prefetched tile into the other stage, then one sync
        if (pf) {
            uint32_t* Kd = smu + ((kt + 1) & 1) * 2 * FSS;
            uint32_t* Vd = Kd + FSS;
            *(uint4*)(Kd + lr * KP2 + lc8)     = kr0;
            *(uint4*)(Kd + lr * KP2 + lc8 + 4) = kr1;
            *(uint4*)(Vd + lr * KP2 + lc8)     = vr0;
            *(uint4*)(Vd + lr * KP2 + lc8 + 4) = vr1;
        }
        __syncthreads();
    }

    // l lives in tm4==0 lanes (col 64 = c0/c2 of nf=8); broadcast within group
    const float l0 = __shfl_sync(0xffffffffu, of[8][0], lane & 28);
    const float l1 = __shfl_sync(0xffffffffu, of[8][2], lane & 28);
    const float inv0 = 1.f / l0;
    const float inv1 = 1.f / l1;

    // epilogue -> g_ao [B,S,N*H] fp16
    const int row0 = qt * 128 + wid * 16 + t4;
    __half* d0 = g_ao + ((size_t)b * S_ + row0) * NHD_ + n * 64;
    __half* d1 = d0 + (size_t)8 * NHD_;
#pragma unroll
    for (int nf = 0; nf < 8; nf++) {
        const int c = nf * 8 + 2 * tm4;
        *(uint32_t*)(d0 + c) = pack2(of[nf][0] * inv0, of[nf][1] * inv0);
        *(uint32_t*)(d1 + c) = pack2(of[nf][2] * inv1, of[nf][3] * inv1);
    }
}

// ---------------------------------------------------------------------------
extern "C" void kernel_launch(void* const* d_in, const int* in_sizes, int n_in,
                              void* d_out, int out_size)
{
    const float* x    = (const float*)d_in[0];
    const float* Wqkv = (const float*)d_in[1];
    const float* bqkv = (const float*)d_in[2];
    const float* Wout = (const float*)d_in[3];
    const float* bout = (const float*)d_in[4];
    float* out = (float*)d_out;

    const int gemm_smem  = (2 * 128 * AP2 + 2 * 16 * BP2) * 4;   // 37888
    const int flash_smem = (4 * FSS) * 4;                        // 36864
    cudaFuncSetAttribute(mma_gemm<1>, cudaFuncAttributeMaxDynamicSharedMemorySize, gemm_smem);
    cudaFuncSetAttribute(mma_gemm<0>, cudaFuncAttributeMaxDynamicSharedMemorySize, gemm_smem);
    cudaFuncSetAttribute(flash_mma, cudaFuncAttributeMaxDynamicSharedMemorySize, flash_smem);

    // prep
    cvt_x_kernel<<<(M_ * E_) / (256 * 8), 256>>>(x);
    pack_w_kernel<1><<<(KD / 2) * QKV_ / 4 / 256, 256>>>(Wqkv);
    pack_w_kernel<0><<<(KD / 2) * NHD_ / 4 / 256, 256>>>(Wout);

    // 1) QKV projection -> g_q, g_k (packed), g_v
    mma_gemm<1><<<dim3(QKV_ / 128, M_ / 128), 128, gemm_smem>>>(bqkv, nullptr);
    // 1b) pack V for flash B-operand
    pack_v_kernel<<<(B_ * NH_ * (S_ / 2) * 32) / 256, 256>>>();
    // 2) causal flash attention (128-query CTAs) -> g_ao
    flash_mma<<<dim3(S_ / 128, B_ * NH_), 256, flash_smem>>>();
    // 3) output projection -> fp32 d_out
    mma_gemm<0><<<dim3(NHD_ / 128, M_ / 128), 128, gemm_smem>>>(bout, out);
}

// round 17
// speedup vs baseline: 1.0469x; 1.0469x over previous
#include <cuda_runtime.h>
#include <cuda_fp16.h>
#include <cstdint>
#include <math.h>

#define B_   4
#define S_   2048
#define E_   1024
#define NH_  16
#define HD_  64
#define M_   (B_ * S_)        // 8192
#define QKV_ (3 * NH_ * HD_)  // 3072
#define NHD_ (NH_ * HD_)      // 1024
#define KD   1024
#define NCH  (KD / 32)        // 32 chunks of 32 k (16 kpairs)
#define AP2  20               // A smem pitch (u32 units)
#define BP2  136              // B smem pitch (u32 units)
#define STG  (128 * AP2 + 16 * BP2)   // u32 per gemm stage = 4736
#define KP2  72               // flash K/V smem pitch (u32)
#define PP2  36               // flash Q-stage pitch (u32)
#define FSS  (32 * KP2)       // flash stage size per operand (u32)
#define SCALE_LOG2E 0.1803368801111204f   // (1/sqrt(64)) * log2(e)

// ---- scratch ----------------------------------------------------------------
// RULE (R3-R10): __device__ globals may ONLY be referenced from device code.
__device__ __half   g_q[B_ * NH_ * S_ * HD_];        // [B,N,S,H]
__device__ uint32_t g_k[B_ * NH_ * (HD_ / 2) * S_];  // [B,N,H/2,S] packed half2(d,d+1)
__device__ __half   g_v[B_ * NH_ * S_ * HD_];        // [B,N,S,H]
__device__ uint32_t g_vp[B_ * NH_ * (S_ / 2) * HD_]; // [B,N,S/2,H] packed half2(s,s+1)
__device__ __half   g_ao[B_ * S_ * NHD_];            // [B,S,N*H]
__device__ __half   g_xh[M_ * E_];                   // x in fp16
__device__ uint32_t g_wqp[(KD / 2) * QKV_];          // W_qkv packed half2-kpair
__device__ uint32_t g_wop[(KD / 2) * NHD_];          // W_out packed

// ---------------- helpers ---------------------------------------------------
__device__ __forceinline__ uint32_t smem_u32(const void* p) {
    uint32_t a;
    asm("{ .reg .u64 t; cvta.to.shared.u64 t, %1; cvt.u32.u64 %0, t; }" : "=r"(a) : "l"(p));
    return a;
}
__device__ __forceinline__ uint32_t pack2(float lo, float hi) {
    uint32_t r;
    asm("cvt.rn.f16x2.f32 %0, %1, %2;" : "=r"(r) : "f"(hi), "f"(lo));
    return r;
}
__device__ __forceinline__ float ex2f(float x) {
    float r;
    asm("ex2.approx.f32 %0, %1;" : "=f"(r) : "f"(x));
    return r;
}
__device__ __forceinline__ uint32_t ex2h2(uint32_t x) {
    uint32_t r;
    asm("ex2.approx.f16x2 %0, %1;" : "=r"(r) : "r"(x));
    return r;
}
#define CP16(dst, src)  asm volatile("cp.async.cg.shared.global [%0], [%1], 16;" :: "r"(dst), "l"(src))
#define CP_COMMIT()     asm volatile("cp.async.commit_group;" ::: "memory")
#define CP_WAIT(n)      asm volatile("cp.async.wait_group %0;" :: "n"(n) : "memory")
#define MMA_F16(c0, c1, c2, c3, a0, a1, a2, a3, b0, b1)                       \
    asm volatile(                                                             \
        "mma.sync.aligned.m16n8k16.row.col.f32.f16.f16.f32 "                  \
        "{%0,%1,%2,%3}, {%4,%5,%6,%7}, {%8,%9}, {%0,%1,%2,%3};"               \
        : "+f"(c0), "+f"(c1), "+f"(c2), "+f"(c3)                              \
        : "r"(a0), "r"(a1), "r"(a2), "r"(a3), "r"(b0), "r"(b1))

// ---------------------------------------------------------------------------
// prep: x (fp32) -> g_xh (fp16)
__global__ __launch_bounds__(256)
void cvt_x_kernel(const float* __restrict__ x)
{
    const size_t i = ((size_t)blockIdx.x * 256 + threadIdx.x) * 8;
    const float4 v0 = *(const float4*)(x + i);
    const float4 v1 = *(const float4*)(x + i + 4);
    uint4 o;
    o.x = pack2(v0.x, v0.y); o.y = pack2(v0.z, v0.w);
    o.z = pack2(v1.x, v1.y); o.w = pack2(v1.z, v1.w);
    *(uint4*)(g_xh + i) = o;
}
// prep: W [K][NW] fp32 -> g_wqp/g_wop packed half2-kpair
template <int MODE>
__global__ __launch_bounds__(256)
void pack_w_kernel(const float* __restrict__ W)
{
    const int NW = (MODE == 1) ? QKV_ : NHD_;
    uint32_t* Wp = (MODE == 1) ? g_wqp : g_wop;
    const int i  = blockIdx.x * 256 + threadIdx.x;
    const int kp = i / (NW / 4);
    const int c4 = (i % (NW / 4)) * 4;
    const float* w0 = W + (size_t)(2 * kp) * NW + c4;
    const float4 a = *(const float4*)w0;
    const float4 b = *(const float4*)(w0 + NW);
    uint4 o;
    o.x = pack2(a.x, b.x); o.y = pack2(a.y, b.y);
    o.z = pack2(a.z, b.z); o.w = pack2(a.w, b.w);
    *(uint4*)(Wp + (size_t)kp * NW + c4) = o;
}
// prep: g_v -> g_vp [B,N,S/2,H]: vp[sp][h] = half2(V[2sp][h], V[2sp+1][h])
__global__ __launch_bounds__(256)
void pack_v_kernel()
{
    const int i   = blockIdx.x * 256 + threadIdx.x;
    const int h2  = i & 31;
    const int spg = i >> 5;
    const int bn  = spg >> 10;
    const int spl = spg & 1023;
    const uint32_t* v32 = (const uint32_t*)g_v;
    const uint32_t a = v32[((size_t)bn * S_ + 2 * spl) * 32 + h2];
    const uint32_t b = v32[((size_t)bn * S_ + 2 * spl + 1) * 32 + h2];
    uint2 o;
    o.x = __byte_perm(a, b, 0x5410);
    o.y = __byte_perm(a, b, 0x7632);
    *(uint2*)(g_vp + (size_t)spg * 64 + 2 * h2) = o;
}

// ---------------------------------------------------------------------------
// FP16 mma.sync GEMM: 4 warps, warp tile 64x64, CTA tile 128x128.
// R17: cp.async 3-stage pipeline (no prefetch registers -> lower reg count,
// more CTAs/SM; global->smem off the register file).
#define GEMM_LOAD(st, c) do {                                                 \
    const uint32_t _sA = smemb + (uint32_t)(st) * (STG * 4);                  \
    const uint32_t _sB = _sA + 128 * AP2 * 4;                                 \
    const int _kh = (c) * 32;                                                 \
    const int _kr = (c) * 16;                                                 \
    _Pragma("unroll")                                                         \
    for (int _q = 0; _q < 4; _q++) {                                          \
        CP16(_sA + (uint32_t)(((ar + _q * 32) * AP2 + aseg) * 4),             \
             Ap + (size_t)(_q * 32) * KD + _kh);                              \
        CP16(_sB + (uint32_t)(((brow + _q * 4) * BP2 + bc4) * 4),             \
             Bp + (size_t)(_kr + _q * 4) * NW);                               \
    }                                                                         \
    CP_COMMIT();                                                              \
} while (0)

template <int MODE>
__global__ __launch_bounds__(128)
void mma_gemm(const float* __restrict__ bias, float* __restrict__ Cout)
{
    const int NW = (MODE == 1) ? QKV_ : NHD_;
    const uint32_t* __restrict__ Wp = (MODE == 1) ? g_wqp : g_wop;
    extern __shared__ uint32_t smu[];
    const uint32_t smemb = smem_u32(smu);

    const int tid  = threadIdx.x;
    const int wid  = tid >> 5;
    const int lane = tid & 31;
    const int warpM = wid & 1;
    const int warpN = wid >> 1;
    const int t4  = lane >> 2;
    const int tm4 = lane & 3;

    const int bn = blockIdx.x * 128, bm = blockIdx.y * 128;
    const __half* Ag = (MODE == 1) ? g_xh : g_ao;

    // loader geometry
    const int ar   = (tid >> 2);           // A row 0..31 (+32 per q)
    const int aseg = (tid & 3) * 4;        // A u32 seg
    const int brow = (tid >> 5);           // B kpair 0..3 (+4 per q)
    const int bc4  = (tid & 31) * 4;       // B col
    const __half*   Ap = Ag + (size_t)(bm + ar) * KD + aseg * 2;
    const uint32_t* Bp = Wp + (size_t)brow * NW + bn + bc4;

    float acc[4][8][4];
#pragma unroll
    for (int mf = 0; mf < 4; mf++)
#pragma unroll
        for (int nf = 0; nf < 8; nf++)
#pragma unroll
            for (int e = 0; e < 4; e++) acc[mf][nf][e] = 0.f;

    GEMM_LOAD(0, 0);
    GEMM_LOAD(1, 1);

    for (int ch = 0; ch < NCH; ch++) {
        if (ch + 1 < NCH) CP_WAIT(1);      // stage ch complete, ch+1 in flight
        else              CP_WAIT(0);
        __syncthreads();

        const uint32_t* Sa = smu + (ch % 3) * STG;
        const uint32_t* Sb = Sa + 128 * AP2;
#pragma unroll
        for (int s = 0; s < 2; s++) {
            const int kk = s * 8;
            uint32_t a[4][4], b[8][2];
#pragma unroll
            for (int mf = 0; mf < 4; mf++) {
                const uint32_t* pav = Sa + (warpM * 64 + mf * 16 + t4) * AP2 + kk + tm4;
                a[mf][0] = pav[0];
                a[mf][1] = pav[8 * AP2];
                a[mf][2] = pav[4];
                a[mf][3] = pav[8 * AP2 + 4];
            }
#pragma unroll
            for (int nf = 0; nf < 8; nf++) {
                const uint32_t* pbv = Sb + (kk + tm4) * BP2 + warpN * 64 + nf * 8 + t4;
                b[nf][0] = pbv[0];
                b[nf][1] = pbv[4 * BP2];
            }
#pragma unroll
            for (int mf = 0; mf < 4; mf++)
#pragma unroll
                for (int nf = 0; nf < 8; nf++)
                    MMA_F16(acc[mf][nf][0], acc[mf][nf][1], acc[mf][nf][2], acc[mf][nf][3],
                            a[mf][0], a[mf][1], a[mf][2], a[mf][3],
                            b[nf][0], b[nf][1]);
        }

        // issue load for ch+2 into stage (ch+2)%3. Readers of that stage
        // (compute ch-1) are behind this iteration's barrier -> safe.
        if (ch + 2 < NCH) GEMM_LOAD((ch + 2) % 3, ch + 2);
    }

    // ---- epilogue
#pragma unroll
    for (int mf = 0; mf < 4; mf++) {
#pragma unroll
        for (int nf = 0; nf < 8; nf++) {
            const int col = bn + warpN * 64 + nf * 8 + 2 * tm4;
            const float2 bv = *(const float2*)(bias + col);
#pragma unroll
            for (int half_ = 0; half_ < 2; half_++) {
                const int m = bm + warpM * 64 + mf * 16 + t4 + half_ * 8;
                const float ox = acc[mf][nf][half_ * 2 + 0] + bv.x;
                const float oy = acc[mf][nf][half_ * 2 + 1] + bv.y;
                if (MODE == 0) {
                    *(float2*)(Cout + (size_t)m * NHD_ + col) = make_float2(ox, oy);
                } else {
                    const int b = m >> 11;
                    const int s = m & (S_ - 1);
                    const int which = col >> 10;
                    const int rem   = col & 1023;
                    const int n = rem >> 6;
                    const int h = rem & 63;
                    if (which == 1) {
                        g_k[((size_t)(b * NH_ + n) * (HD_ / 2) + (h >> 1)) * S_ + s] =
                            pack2(ox, oy);
                    } else {
                        __half* dst = (which == 0) ? g_q : g_v;
                        *(uint32_t*)(dst + (((size_t)b * NH_ + n) * S_ + s) * HD_ + h) =
                            pack2(ox, oy);
                    }
                }
            }
        }
    }
}

// ---------------------------------------------------------------------------
// FP16 mma.sync causal flash attention (R15 version — best so far).
__global__ __launch_bounds__(128)
void flash_mma()
{
    extern __shared__ uint32_t smu[];

    const int tid  = threadIdx.x;
    const int wid  = tid >> 5;
    const int lane = tid & 31;
    const int t4   = lane >> 2;
    const int tm4  = lane & 3;
    const int qt   = gridDim.x - 1 - blockIdx.x;   // big causal tiles first
    const int bn   = blockIdx.y;
    const int b    = bn >> 4;
    const int n    = bn & 15;

    const __half*   Qg  = g_q + ((size_t)bn * S_ + (size_t)qt * 64) * HD_;
    const uint32_t* KgT = g_k + (size_t)bn * 32 * S_;
    const uint32_t* VgP = g_vp + (size_t)bn * (S_ / 2) * 64;

    // stage Q (transiently in K-stage0 area), build register fragments
    {
        const int row = tid >> 1;
        const int c0  = (tid & 1) * 16;
        const uint32_t* src = (const uint32_t*)(Qg + (size_t)row * HD_) + c0;
        uint32_t* dst = smu + row * PP2 + c0;
#pragma unroll
        for (int i = 0; i < 4; i++) ((uint4*)dst)[i] = ((const uint4*)src)[i];
    }
    __syncwarp();
    uint32_t qf[4][4];
#pragma unroll
    for (int s = 0; s < 4; s++) {
        const uint32_t* p = smu + (wid * 16 + t4) * PP2 + s * 8 + tm4;
        qf[s][0] = p[0];
        qf[s][1] = p[8 * PP2];
        qf[s][2] = p[4];
        qf[s][3] = p[8 * PP2 + 4];
    }
    __syncthreads();   // Q fully consumed before stage area is rewritten

    const int lr = tid >> 2;
    const int lc = (tid & 3) * 4;

    // ones-column init: Vs col 64 = half2(1,1), cols 65..71 = 0 (both stages)
#pragma unroll
    for (int i = 0; i < 4; i++) {
        const int idx   = tid + i * 128;
        const int row   = idx & 31;
        const int cc    = (idx >> 5) & 7;
        const int stage = idx >> 8;
        smu[stage * 2 * FSS + FSS + row * KP2 + 64 + cc] =
            (cc == 0) ? 0x3C003C00u : 0u;
    }

    // prologue: tile kt=0 -> stage 0
#pragma unroll
    for (int i = 0; i < 4; i++) {
        const int c = lc + 16 * i;
        *(uint4*)(smu + lr * KP2 + c) =
            *(const uint4*)(KgT + (size_t)lr * S_ + c);
        *(uint4*)(smu + FSS + lr * KP2 + c) =
            *(const uint4*)(VgP + (size_t)lr * 64 + c);
    }
    __syncthreads();

    // of[0..7] = O columns; of[8] = l (ones-column accumulator)
    float of[9][4];
#pragma unroll
    for (int nf = 0; nf < 9; nf++)
#pragma unroll
        for (int e = 0; e < 4; e++) of[nf][e] = 0.f;
    float m0 = -1e30f, m1 = -1e30f;

    const int nK = qt + 1;
    for (int kt = 0; kt < nK; kt++) {
        // prefetch next K/V tile into registers (overlaps MMAs)
        uint4 kr[4], vr[4];
        const bool pf = (kt + 1 < nK);
        if (pf) {
#pragma unroll
            for (int i = 0; i < 4; i++) {
                const int c = lc + 16 * i;
                kr[i] = *(const uint4*)(KgT + (size_t)lr * S_ + (kt + 1) * 64 + c);
                vr[i] = *(const uint4*)(VgP + (size_t)((kt + 1) * 32 + lr) * 64 + c);
            }
        }

        const uint32_t* Ks = smu + (kt & 1) * 2 * FSS;
        const uint32_t* Vs = Ks + FSS;

        // S = Q K^T
        float sf[8][4];
#pragma unroll
        for (int nf = 0; nf < 8; nf++)
#pragma unroll
            for (int e = 0; e < 4; e++) sf[nf][e] = 0.f;
#pragma unroll
        for (int s = 0; s < 4; s++) {
#pragma unroll
            for (int nf = 0; nf < 8; nf++) {
                const uint32_t* pb = Ks + (s * 8 + tm4) * KP2 + nf * 8 + t4;
                MMA_F16(sf[nf][0], sf[nf][1], sf[nf][2], sf[nf][3],
                        qf[s][0], qf[s][1], qf[s][2], qf[s][3],
                        pb[0], pb[4 * KP2]);
            }
        }

        // scale into exp2 domain + causal mask + row max
        const bool diag = (kt == qt);
        float mn0 = m0, mn1 = m1;
#pragma unroll
        for (int nf = 0; nf < 8; nf++) {
#pragma unroll
            for (int e = 0; e < 4; e++) {
                float v = sf[nf][e] * SCALE_LOG2E;
                if (diag) {
                    const int kcol = nf * 8 + 2 * tm4 + (e & 1);
                    const int qrow = wid * 16 + t4 + ((e >= 2) ? 8 : 0);
                    if (kcol > qrow) v = -1e30f;
                }
                sf[nf][e] = v;
            }
            mn0 = fmaxf(mn0, fmaxf(sf[nf][0], sf[nf][1]));
            mn1 = fmaxf(mn1, fmaxf(sf[nf][2], sf[nf][3]));
        }
        mn0 = fmaxf(mn0, __shfl_xor_sync(0xffffffffu, mn0, 1));
        mn0 = fmaxf(mn0, __shfl_xor_sync(0xffffffffu, mn0, 2));
        mn1 = fmaxf(mn1, __shfl_xor_sync(0xffffffffu, mn1, 1));
        mn1 = fmaxf(mn1, __shfl_xor_sync(0xffffffffu, mn1, 2));
        const float corr0 = ex2f(m0 - mn0);
        const float corr1 = ex2f(m1 - mn1);
        m0 = mn0; m1 = mn1;

        // exp2 in fp16x2: output = packed P A-fragment directly
        uint32_t pfr[8][2];
#pragma unroll
        for (int nf = 0; nf < 8; nf++) {
            pfr[nf][0] = ex2h2(pack2(sf[nf][0] - mn0, sf[nf][1] - mn0));
            pfr[nf][1] = ex2h2(pack2(sf[nf][2] - mn1, sf[nf][3] - mn1));
        }
        // rescale O and l accumulators
#pragma unroll
        for (int nf = 0; nf < 9; nf++) {
            of[nf][0] *= corr0; of[nf][1] *= corr0;
            of[nf][2] *= corr1; of[nf][3] *= corr1;
        }

        // O += P V  and  l += P . ones   (nf = 8 reads the ones column)
#pragma unroll
        for (int s = 0; s < 4; s++) {
            const uint32_t a0 = pfr[2 * s][0];
            const uint32_t a1 = pfr[2 * s][1];
            const uint32_t a2 = pfr[2 * s + 1][0];
            const uint32_t a3 = pfr[2 * s + 1][1];
#pragma unroll
            for (int nf = 0; nf < 9; nf++) {
                const uint32_t* pv = Vs + (s * 8 + tm4) * KP2 + nf * 8 + t4;
                MMA_F16(of[nf][0], of[nf][1], of[nf][2], of[nf][3],
                        a0, a1, a2, a3, pv[0], pv[4 * KP2]);
            }
        }

        // store prefetched tile into the other stage, then one sync
        if (pf) {
            uint32_t* Kd = smu + ((kt + 1) & 1) * 2 * FSS;
            uint32_t* Vd = Kd + FSS;
#pragma unroll
            for (int i = 0; i < 4; i++) {
                const int c = lc + 16 * i;
                *(uint4*)(Kd + lr * KP2 + c) = kr[i];
                *(uint4*)(Vd + lr * KP2 + c) = vr[i];
            }
        }
        __syncthreads();
    }

    // l lives in tm4==0 lanes (col 64 = c0/c2 of nf=8); broadcast within group
    const float l0 = __shfl_sync(0xffffffffu, of[8][0], lane & 28);
    const float l1 = __shfl_sync(0xffffffffu, of[8][2], lane & 28);
    const float inv0 = 1.f / l0;
    const float inv1 = 1.f / l1;

    // epilogue -> g_ao [B,S,N*H] fp16
    const int row0 = qt * 64 + wid * 16 + t4;
    __half* d0 = g_ao + ((size_t)b * S_ + row0) * NHD_ + n * 64;
    __half* d1 = d0 + (size_t)8 * NHD_;
#pragma unroll
    for (int nf = 0; nf < 8; nf++) {
        const int c = nf * 8 + 2 * tm4;
        *(uint32_t*)(d0 + c) = pack2(of[nf][0] * inv0, of[nf][1] * inv0);
        *(uint32_t*)(d1 + c) = pack2(of[nf][2] * inv1, of[nf][3] * inv1);
    }
}

// ---------------------------------------------------------------------------
extern "C" void kernel_launch(void* const* d_in, const int* in_sizes, int n_in,
                              void* d_out, int out_size)
{
    const float* x    = (const float*)d_in[0];
    const float* Wqkv = (const float*)d_in[1];
    const float* bqkv = (const float*)d_in[2];
    const float* Wout = (const float*)d_in[3];
    const float* bout = (const float*)d_in[4];
    float* out = (float*)d_out;

    const int gemm_smem  = 3 * STG * 4;        // 56832
    const int flash_smem = (4 * FSS) * 4;      // 36864
    cudaFuncSetAttribute(mma_gemm<1>, cudaFuncAttributeMaxDynamicSharedMemorySize, gemm_smem);
    cudaFuncSetAttribute(mma_gemm<0>, cudaFuncAttributeMaxDynamicSharedMemorySize, gemm_smem);
    cudaFuncSetAttribute(flash_mma, cudaFuncAttributeMaxDynamicSharedMemorySize, flash_smem);

    // prep
    cvt_x_kernel<<<(M_ * E_) / (256 * 8), 256>>>(x);
    pack_w_kernel<1><<<(KD / 2) * QKV_ / 4 / 256, 256>>>(Wqkv);
    pack_w_kernel<0><<<(KD / 2) * NHD_ / 4 / 256, 256>>>(Wout);

    // 1) QKV projection -> g_q, g_k (packed), g_v
    mma_gemm<1><<<dim3(QKV_ / 128, M_ / 128), 128, gemm_smem>>>(bqkv, nullptr);
    // 1b) pack V for flash B-operand
    pack_v_kernel<<<(B_ * NH_ * (S_ / 2) * 32) / 256, 256>>>();
    // 2) causal flash attention -> g_ao
    flash_mma<<<dim3(S_ / 64, B_ * NH_), 128, flash_smem>>>();
    // 3) output projection -> fp32 d_out
    mma_gemm<0><<<dim3(NHD_ / 128, M_ / 128), 128, gemm_smem>>>(bout, out);
}